// round 2
// baseline (speedup 1.0000x reference)
#include <cuda_runtime.h>
#include <math_constants.h>

#define NN 25600
#define DEG 16
#define EE 409600
#define GB 8
#define FF 7
#define HH 300
#define LL 100
#define BK 20

// ---------------- scratch (static device globals; no runtime allocation) ----
__device__ float g_P[NN * HH];              // per-node  x@(W1a-W1b)+b1
__device__ float g_Q[NN * HH];              // per-node  x@W1b
__device__ float g_h2[EE * (size_t)HH];     // per-edge hidden (491.5 MB)
__device__ float g_node[NN * LL];           // per-node layer output (relu'd)
__device__ float g_pooled[GB * 3 * LL];     // [8, 300]

// ---------------------------------------------------------------------------
// front: per-node first MLP layer, exploiting linearity of concat([x_i, x_j-x_i]).
//   P[n,j] = sum_k x[n,k] * (W[k,j] - W[K+k,j]) + b[j]
//   Q[n,j] = sum_k x[n,k] * W[K+k,j]
// block: 300 threads (one per output col), 16 nodes per block. grid: N/16.
__global__ void front_kernel(const float* __restrict__ xin, int K,
                             const float* __restrict__ W,
                             const float* __restrict__ b,
                             int from_node) {
    __shared__ float xs[16 * 100];
    const float* __restrict__ x = from_node ? g_node : xin;
    int n0 = blockIdx.x * 16;
    int j = threadIdx.x;  // 0..299
    for (int i = threadIdx.x; i < 16 * K; i += 300)
        xs[i] = x[n0 * K + i];
    __syncthreads();

    float accP[16], accQ[16];
    float bj = b[j];
#pragma unroll
    for (int r = 0; r < 16; r++) { accP[r] = bj; accQ[r] = 0.f; }

    for (int k = 0; k < K; k++) {
        float wa = W[k * HH + j];
        float wb = W[(K + k) * HH + j];
        float d = wa - wb;
#pragma unroll
        for (int r = 0; r < 16; r++) {
            float xv = xs[r * K + k];
            accP[r] = fmaf(xv, d, accP[r]);
            accQ[r] = fmaf(xv, wb, accQ[r]);
        }
    }
#pragma unroll
    for (int r = 0; r < 16; r++) {
        g_P[(n0 + r) * HH + j] = accP[r];
        g_Q[(n0 + r) * HH + j] = accQ[r];
    }
}

// ---------------------------------------------------------------------------
// gemm_mid: h2[e, col] = relu( relu(P[e/16]+Q[src[e]]) @ W2 + b2 )
// A-operand generated on the fly (gather), tile BM=128 edges x BN=100 cols, BK=20.
// 320 threads: tx in [0,20) cols (stride-20 x5), ty in [0,16) rows (8 contiguous).
__global__ __launch_bounds__(320) void gemm_mid(const int* __restrict__ src,
                                                const float* __restrict__ W,
                                                const float* __restrict__ bias) {
    __shared__ __align__(16) float As[BK][132];
    __shared__ __align__(16) float Bs[BK][104];
    __shared__ int s_src[128];

    int tid = threadIdx.x;
    int tx = tid % 20, ty = tid / 20;
    int row0 = blockIdx.y * 128;
    int n0 = blockIdx.y * 8;
    int jt0 = blockIdx.x * 100;

    if (tid < 128) s_src[tid] = src[row0 + tid];

    float acc[8][5];
#pragma unroll
    for (int i = 0; i < 8; i++)
#pragma unroll
        for (int j = 0; j < 5; j++) acc[i][j] = 0.f;
    __syncthreads();

    for (int kt = 0; kt < HH; kt += BK) {
        // A tile: 128 rows x 20 k = 640 float4 (gather + add + relu)
        for (int i = tid; i < 640; i += 320) {
            int row = i / 5, kq = i % 5;
            int nid = n0 + (row >> 4);
            int sid = s_src[row];
            int off = kt + kq * 4;
            float4 p = *(const float4*)&g_P[nid * HH + off];
            float4 q = *(const float4*)&g_Q[sid * HH + off];
            As[kq * 4 + 0][row] = fmaxf(p.x + q.x, 0.f);
            As[kq * 4 + 1][row] = fmaxf(p.y + q.y, 0.f);
            As[kq * 4 + 2][row] = fmaxf(p.z + q.z, 0.f);
            As[kq * 4 + 3][row] = fmaxf(p.w + q.w, 0.f);
        }
        // B tile: 20 x 100 = 500 float4
        for (int i = tid; i < 500; i += 320) {
            int k = i / 25, jq = i % 25;
            float4 w = *(const float4*)&W[(kt + k) * HH + jt0 + jq * 4];
            Bs[k][jq * 4 + 0] = w.x;
            Bs[k][jq * 4 + 1] = w.y;
            Bs[k][jq * 4 + 2] = w.z;
            Bs[k][jq * 4 + 3] = w.w;
        }
        __syncthreads();
#pragma unroll
        for (int kk = 0; kk < BK; kk++) {
            float4 a0 = *(const float4*)&As[kk][ty * 8];
            float4 a1 = *(const float4*)&As[kk][ty * 8 + 4];
            float a[8] = {a0.x, a0.y, a0.z, a0.w, a1.x, a1.y, a1.z, a1.w};
            float bf[5];
#pragma unroll
            for (int j = 0; j < 5; j++) bf[j] = Bs[kk][tx + 20 * j];
#pragma unroll
            for (int i = 0; i < 8; i++)
#pragma unroll
                for (int j = 0; j < 5; j++)
                    acc[i][j] = fmaf(a[i], bf[j], acc[i][j]);
        }
        __syncthreads();
    }

#pragma unroll
    for (int j = 0; j < 5; j++) {
        int col = jt0 + tx + 20 * j;
        float bb = bias[col];
#pragma unroll
        for (int i = 0; i < 8; i++) {
            int row = row0 + ty * 8 + i;
            g_h2[(size_t)row * HH + col] = fmaxf(acc[i][j] + bb, 0.f);
        }
    }
}

// ---------------------------------------------------------------------------
// gemm_out: h3 = h2 @ W3 + b3 [E,100], fused max over 16-row groups + relu
//   -> g_node[n, col] = relu( max_{e in node n} h3[e,col] + b3[col] )
__global__ __launch_bounds__(320) void gemm_out(const float* __restrict__ W,
                                                const float* __restrict__ bias) {
    __shared__ __align__(16) float As[BK][132];
    __shared__ __align__(16) float Bs[BK][104];
    __shared__ float red[16][100];

    int tid = threadIdx.x;
    int tx = tid % 20, ty = tid / 20;
    int row0 = blockIdx.x * 128;
    int n0 = blockIdx.x * 8;

    float acc[8][5];
#pragma unroll
    for (int i = 0; i < 8; i++)
#pragma unroll
        for (int j = 0; j < 5; j++) acc[i][j] = 0.f;

    for (int kt = 0; kt < HH; kt += BK) {
        for (int i = tid; i < 640; i += 320) {
            int row = i / 5, kq = i % 5;
            float4 v = *(const float4*)&g_h2[(size_t)(row0 + row) * HH + kt + kq * 4];
            As[kq * 4 + 0][row] = v.x;
            As[kq * 4 + 1][row] = v.y;
            As[kq * 4 + 2][row] = v.z;
            As[kq * 4 + 3][row] = v.w;
        }
        for (int i = tid; i < 500; i += 320) {
            int k = i / 25, jq = i % 25;
            float4 w = *(const float4*)&W[(kt + k) * LL + jq * 4];
            Bs[k][jq * 4 + 0] = w.x;
            Bs[k][jq * 4 + 1] = w.y;
            Bs[k][jq * 4 + 2] = w.z;
            Bs[k][jq * 4 + 3] = w.w;
        }
        __syncthreads();
#pragma unroll
        for (int kk = 0; kk < BK; kk++) {
            float4 a0 = *(const float4*)&As[kk][ty * 8];
            float4 a1 = *(const float4*)&As[kk][ty * 8 + 4];
            float a[8] = {a0.x, a0.y, a0.z, a0.w, a1.x, a1.y, a1.z, a1.w};
            float bf[5];
#pragma unroll
            for (int j = 0; j < 5; j++) bf[j] = Bs[kk][tx + 20 * j];
#pragma unroll
            for (int i = 0; i < 8; i++)
#pragma unroll
                for (int j = 0; j < 5; j++)
                    acc[i][j] = fmaf(a[i], bf[j], acc[i][j]);
        }
        __syncthreads();
    }

    // thread-local max over its 8 contiguous rows (half a 16-edge node group)
#pragma unroll
    for (int j = 0; j < 5; j++) {
        int col = tx + 20 * j;
        float m = acc[0][j];
#pragma unroll
        for (int i = 1; i < 8; i++) m = fmaxf(m, acc[i][j]);
        red[ty][col] = m;
    }
    __syncthreads();
    if (ty < 8) {
#pragma unroll
        for (int j = 0; j < 5; j++) {
            int col = tx + 20 * j;
            float m = fmaxf(red[2 * ty][col], red[2 * ty + 1][col]);
            g_node[(n0 + ty) * LL + col] = fmaxf(m + bias[col], 0.f);
        }
    }
}

// ---------------------------------------------------------------------------
// pool: per-graph (3200 consecutive nodes) sum / mean / max over g_node[N,100]
// grid: 8 graphs, block: 800 threads = 8 node-partitions x 100 cols
__global__ void pool_kernel() {
    __shared__ float ssum[8][100];
    __shared__ float smax[8][100];
    int g = blockIdx.x;
    int col = threadIdx.x % 100;
    int part = threadIdx.x / 100;
    float s = 0.f, m = -CUDART_INF_F;
    int base = g * 3200 + part * 400;
    for (int n = 0; n < 400; n++) {
        float v = g_node[(base + n) * LL + col];
        s += v;
        m = fmaxf(m, v);
    }
    ssum[part][col] = s;
    smax[part][col] = m;
    __syncthreads();
    if (part == 0) {
        for (int p = 1; p < 8; p++) {
            s += ssum[p][col];
            m = fmaxf(m, smax[p][col]);
        }
        g_pooled[g * 300 + col] = s;
        g_pooled[g * 300 + 100 + col] = s / 3200.0f;
        g_pooled[g * 300 + 200 + col] = m;
    }
}

// ---------------------------------------------------------------------------
// head MLP: [8,300] -> relu 100 -> relu 100 -> 1. One block, 128 threads.
__global__ void final_kernel(const float* __restrict__ W1, const float* __restrict__ b1,
                             const float* __restrict__ W2, const float* __restrict__ b2,
                             const float* __restrict__ W3, const float* __restrict__ b3,
                             float* __restrict__ out) {
    __shared__ float sp[GB * 300];
    __shared__ float t1[GB * 100];
    int j = threadIdx.x;
    for (int i = j; i < GB * 300; i += blockDim.x) sp[i] = g_pooled[i];
    __syncthreads();

    if (j < 100) {
        float acc[GB];
#pragma unroll
        for (int r = 0; r < GB; r++) acc[r] = b1[j];
        for (int k = 0; k < 300; k++) {
            float w = W1[k * 100 + j];
#pragma unroll
            for (int r = 0; r < GB; r++) acc[r] = fmaf(sp[r * 300 + k], w, acc[r]);
        }
#pragma unroll
        for (int r = 0; r < GB; r++) t1[r * 100 + j] = fmaxf(acc[r], 0.f);
    }
    __syncthreads();

    float acc2[GB];
    if (j < 100) {
#pragma unroll
        for (int r = 0; r < GB; r++) acc2[r] = b2[j];
        for (int k = 0; k < 100; k++) {
            float w = W2[k * 100 + j];
#pragma unroll
            for (int r = 0; r < GB; r++) acc2[r] = fmaf(t1[r * 100 + k], w, acc2[r]);
        }
    }
    __syncthreads();  // all reads of t1 done
    if (j < 100) {
#pragma unroll
        for (int r = 0; r < GB; r++) sp[r * 100 + j] = fmaxf(acc2[r], 0.f);
    }
    __syncthreads();

    if (j < GB) {
        float s = b3[0];
        for (int k = 0; k < 100; k++) s = fmaf(sp[j * 100 + k], W3[k], s);
        out[j] = s;
    }
}

// ---------------------------------------------------------------------------
extern "C" void kernel_launch(void* const* d_in, const int* in_sizes, int n_in,
                              void* d_out, int out_size) {
    const float* x        = (const float*)d_in[0];
    const int*   eidx     = (const int*)d_in[1];   // [2,E]: row0=src, row1=dst
    const float* l0_W1 = (const float*)d_in[3];
    const float* l0_b1 = (const float*)d_in[4];
    const float* l0_W2 = (const float*)d_in[5];
    const float* l0_b2 = (const float*)d_in[6];
    const float* l0_W3 = (const float*)d_in[7];
    const float* l0_b3 = (const float*)d_in[8];
    const float* l1_W1 = (const float*)d_in[9];
    const float* l1_b1 = (const float*)d_in[10];
    const float* l1_W2 = (const float*)d_in[11];
    const float* l1_b2 = (const float*)d_in[12];
    const float* l1_W3 = (const float*)d_in[13];
    const float* l1_b3 = (const float*)d_in[14];
    const float* lin_W1 = (const float*)d_in[15];
    const float* lin_b1 = (const float*)d_in[16];
    const float* lin_W2 = (const float*)d_in[17];
    const float* lin_b2 = (const float*)d_in[18];
    const float* lin_W3 = (const float*)d_in[19];
    const float* lin_b3 = (const float*)d_in[20];

    const int* src = eidx;  // first row of edge_index

    // ---- layer 0 ----
    front_kernel<<<NN / 16, 300>>>(x, FF, l0_W1, l0_b1, 0);
    gemm_mid<<<dim3(3, EE / 128), 320>>>(src, l0_W2, l0_b2);
    gemm_out<<<EE / 128, 320>>>(l0_W3, l0_b3);
    // ---- layer 1 ----
    front_kernel<<<NN / 16, 300>>>(nullptr, LL, l1_W1, l1_b1, 1);
    gemm_mid<<<dim3(3, EE / 128), 320>>>(src, l1_W2, l1_b2);
    gemm_out<<<EE / 128, 320>>>(l1_W3, l1_b3);
    // ---- pooling + head ----
    pool_kernel<<<GB, 800>>>();
    final_kernel<<<1, 128>>>(lin_W1, lin_b1, lin_W2, lin_b2, lin_W3, lin_b3,
                             (float*)d_out);
}

// round 4
// speedup vs baseline: 1.1473x; 1.1473x over previous
#include <cuda_runtime.h>
#include <math_constants.h>

#define NN 25600
#define DEG 16
#define EE 409600
#define GB 8
#define FF 7
#define HH 300
#define LL 100
#define BK 20

typedef unsigned long long u64;

// ---- packed f32x2 helpers (PTX-only path; ptxas never auto-fuses FFMA2) ----
__device__ __forceinline__ u64 pack2(float x, float y) {
    u64 r;
    asm("mov.b64 %0, {%1, %2};" : "=l"(r) : "f"(x), "f"(y));
    return r;
}
__device__ __forceinline__ void ffma2(u64& d, u64 a, u64 b) {
    asm("fma.rn.f32x2 %0, %1, %2, %0;" : "+l"(d) : "l"(a), "l"(b));
}
__device__ __forceinline__ float2 unpack2(u64 v) {
    float2 r;
    asm("mov.b64 {%0, %1}, %2;" : "=f"(r.x), "=f"(r.y) : "l"(v));
    return r;
}

// ---------------- scratch (static device globals; no runtime allocation) ----
__device__ float g_P[NN * HH];              // per-node  x@(W1a-W1b)+b1
__device__ float g_Q[NN * HH];              // per-node  x@W1b
__device__ float g_h2[EE * (size_t)HH];     // per-edge hidden (491.5 MB)
__device__ float g_node[NN * LL];           // per-node layer output (relu'd)
__device__ float g_pooled[GB * 3 * LL];     // [8, 300]

// ---------------------------------------------------------------------------
// front: per-node first MLP layer, exploiting linearity of concat([x_i, x_j-x_i]).
//   P[n,j] = sum_k x[n,k] * (W[k,j] - W[K+k,j]) + b[j]
//   Q[n,j] = sum_k x[n,k] * W[K+k,j]
// block: 300 threads (one per output col), 16 nodes per block. grid: N/16.
// Row pairs packed into f32x2 accumulators.
__global__ void front_kernel(const float* __restrict__ xin, int K,
                             const float* __restrict__ W,
                             const float* __restrict__ b,
                             int from_node) {
    __shared__ float xs[16 * 100];
    const float* __restrict__ x = from_node ? g_node : xin;
    int n0 = blockIdx.x * 16;
    int j = threadIdx.x;  // 0..299
    for (int i = threadIdx.x; i < 16 * K; i += 300)
        xs[i] = x[n0 * K + i];
    __syncthreads();

    float bj = b[j];
    u64 pP[8], pQ[8];
    u64 bj2 = pack2(bj, bj);
    u64 z2 = pack2(0.f, 0.f);
#pragma unroll
    for (int r = 0; r < 8; r++) { pP[r] = bj2; pQ[r] = z2; }

    for (int k = 0; k < K; k++) {
        float wa = W[k * HH + j];
        float wb = W[(K + k) * HH + j];
        float d = wa - wb;
        u64 dd = pack2(d, d);
        u64 ww = pack2(wb, wb);
#pragma unroll
        for (int r = 0; r < 8; r++) {
            u64 xp = pack2(xs[(2 * r) * K + k], xs[(2 * r + 1) * K + k]);
            ffma2(pP[r], xp, dd);
            ffma2(pQ[r], xp, ww);
        }
    }
#pragma unroll
    for (int r = 0; r < 8; r++) {
        float2 vp = unpack2(pP[r]);
        float2 vq = unpack2(pQ[r]);
        g_P[(n0 + 2 * r) * HH + j] = vp.x;
        g_P[(n0 + 2 * r + 1) * HH + j] = vp.y;
        g_Q[(n0 + 2 * r) * HH + j] = vq.x;
        g_Q[(n0 + 2 * r + 1) * HH + j] = vq.y;
    }
}

// ---------------------------------------------------------------------------
// gemm_mid: h2[e, col] = relu( relu(P[e/16]+Q[src[e]]) @ W2 + b2 )
// A-operand generated on the fly (gather), tile BM=128 edges x BN=100 cols, BK=20.
// 320 threads: tx in [0,20) cols (stride-20 x5), ty in [0,16) rows (8 contiguous).
// Accumulators: 4 row-pairs x 5 cols packed f32x2.
__global__ __launch_bounds__(320) void gemm_mid(const int* __restrict__ src,
                                                const float* __restrict__ W,
                                                const float* __restrict__ bias) {
    __shared__ __align__(16) float As[BK][132];
    __shared__ __align__(16) float Bs[BK][104];
    __shared__ int s_src[128];

    int tid = threadIdx.x;
    int tx = tid % 20, ty = tid / 20;
    int row0 = blockIdx.y * 128;
    int n0 = blockIdx.y * 8;
    int jt0 = blockIdx.x * 100;

    if (tid < 128) s_src[tid] = src[row0 + tid];

    u64 acc[4][5];
    u64 z2 = pack2(0.f, 0.f);
#pragma unroll
    for (int i = 0; i < 4; i++)
#pragma unroll
        for (int j = 0; j < 5; j++) acc[i][j] = z2;
    __syncthreads();

    for (int kt = 0; kt < HH; kt += BK) {
        // A tile: 128 rows x 20 k = 640 float4 (gather + add + relu)
        for (int i = tid; i < 640; i += 320) {
            int row = i / 5, kq = i % 5;
            int nid = n0 + (row >> 4);
            int sid = s_src[row];
            int off = kt + kq * 4;
            float4 p = *(const float4*)&g_P[nid * HH + off];
            float4 q = *(const float4*)&g_Q[sid * HH + off];
            As[kq * 4 + 0][row] = fmaxf(p.x + q.x, 0.f);
            As[kq * 4 + 1][row] = fmaxf(p.y + q.y, 0.f);
            As[kq * 4 + 2][row] = fmaxf(p.z + q.z, 0.f);
            As[kq * 4 + 3][row] = fmaxf(p.w + q.w, 0.f);
        }
        // B tile: 20 x 100 = 500 float4
        for (int i = tid; i < 500; i += 320) {
            int k = i / 25, jq = i % 25;
            float4 w = *(const float4*)&W[(kt + k) * HH + jt0 + jq * 4];
            Bs[k][jq * 4 + 0] = w.x;
            Bs[k][jq * 4 + 1] = w.y;
            Bs[k][jq * 4 + 2] = w.z;
            Bs[k][jq * 4 + 3] = w.w;
        }
        __syncthreads();
#pragma unroll
        for (int kk = 0; kk < BK; kk++) {
            ulonglong2 aA = *(const ulonglong2*)&As[kk][ty * 8];
            ulonglong2 aB = *(const ulonglong2*)&As[kk][ty * 8 + 4];
            u64 ap[4] = {aA.x, aA.y, aB.x, aB.y};
            u64 bb[5];
#pragma unroll
            for (int j = 0; j < 5; j++) {
                float bv = Bs[kk][tx + 20 * j];
                bb[j] = pack2(bv, bv);
            }
#pragma unroll
            for (int i = 0; i < 4; i++)
#pragma unroll
                for (int j = 0; j < 5; j++)
                    ffma2(acc[i][j], ap[i], bb[j]);
        }
        __syncthreads();
    }

#pragma unroll
    for (int j = 0; j < 5; j++) {
        int col = jt0 + tx + 20 * j;
        float bb = bias[col];
#pragma unroll
        for (int i = 0; i < 4; i++) {
            float2 v = unpack2(acc[i][j]);
            int row = row0 + ty * 8 + 2 * i;
            g_h2[(size_t)row * HH + col] = fmaxf(v.x + bb, 0.f);
            g_h2[(size_t)(row + 1) * HH + col] = fmaxf(v.y + bb, 0.f);
        }
    }
}

// ---------------------------------------------------------------------------
// gemm_out: h3 = h2 @ W3 + b3 [E,100], fused max over 16-row groups + relu
//   -> g_node[n, col] = relu( max_{e in node n} h3[e,col] + b3[col] )
__global__ __launch_bounds__(320) void gemm_out(const float* __restrict__ W,
                                                const float* __restrict__ bias) {
    __shared__ __align__(16) float As[BK][132];
    __shared__ __align__(16) float Bs[BK][104];
    __shared__ float red[16][100];

    int tid = threadIdx.x;
    int tx = tid % 20, ty = tid / 20;
    int row0 = blockIdx.x * 128;
    int n0 = blockIdx.x * 8;

    u64 acc[4][5];
    u64 z2 = pack2(0.f, 0.f);
#pragma unroll
    for (int i = 0; i < 4; i++)
#pragma unroll
        for (int j = 0; j < 5; j++) acc[i][j] = z2;

    for (int kt = 0; kt < HH; kt += BK) {
        for (int i = tid; i < 640; i += 320) {
            int row = i / 5, kq = i % 5;
            float4 v = *(const float4*)&g_h2[(size_t)(row0 + row) * HH + kt + kq * 4];
            As[kq * 4 + 0][row] = v.x;
            As[kq * 4 + 1][row] = v.y;
            As[kq * 4 + 2][row] = v.z;
            As[kq * 4 + 3][row] = v.w;
        }
        for (int i = tid; i < 500; i += 320) {
            int k = i / 25, jq = i % 25;
            float4 w = *(const float4*)&W[(kt + k) * LL + jq * 4];
            Bs[k][jq * 4 + 0] = w.x;
            Bs[k][jq * 4 + 1] = w.y;
            Bs[k][jq * 4 + 2] = w.z;
            Bs[k][jq * 4 + 3] = w.w;
        }
        __syncthreads();
#pragma unroll
        for (int kk = 0; kk < BK; kk++) {
            ulonglong2 aA = *(const ulonglong2*)&As[kk][ty * 8];
            ulonglong2 aB = *(const ulonglong2*)&As[kk][ty * 8 + 4];
            u64 ap[4] = {aA.x, aA.y, aB.x, aB.y};
            u64 bb[5];
#pragma unroll
            for (int j = 0; j < 5; j++) {
                float bv = Bs[kk][tx + 20 * j];
                bb[j] = pack2(bv, bv);
            }
#pragma unroll
            for (int i = 0; i < 4; i++)
#pragma unroll
                for (int j = 0; j < 5; j++)
                    ffma2(acc[i][j], ap[i], bb[j]);
        }
        __syncthreads();
    }

    // thread-local max over its 8 contiguous rows (half a 16-edge node group)
#pragma unroll
    for (int j = 0; j < 5; j++) {
        int col = tx + 20 * j;
        float2 v0 = unpack2(acc[0][j]);
        float2 v1 = unpack2(acc[1][j]);
        float2 v2 = unpack2(acc[2][j]);
        float2 v3 = unpack2(acc[3][j]);
        float m = fmaxf(fmaxf(fmaxf(v0.x, v0.y), fmaxf(v1.x, v1.y)),
                        fmaxf(fmaxf(v2.x, v2.y), fmaxf(v3.x, v3.y)));
        red[ty][col] = m;
    }
    __syncthreads();
    if (ty < 8) {
#pragma unroll
        for (int j = 0; j < 5; j++) {
            int col = tx + 20 * j;
            float m = fmaxf(red[2 * ty][col], red[2 * ty + 1][col]);
            g_node[(n0 + ty) * LL + col] = fmaxf(m + bias[col], 0.f);
        }
    }
}

// ---------------------------------------------------------------------------
// pool: per-graph (3200 consecutive nodes) sum / mean / max over g_node[N,100]
// grid: 8 graphs, block: 800 threads = 8 node-partitions x 100 cols
__global__ void pool_kernel() {
    __shared__ float ssum[8][100];
    __shared__ float smax[8][100];
    int g = blockIdx.x;
    int col = threadIdx.x % 100;
    int part = threadIdx.x / 100;
    float s = 0.f, m = -CUDART_INF_F;
    int base = g * 3200 + part * 400;
    for (int n = 0; n < 400; n++) {
        float v = g_node[(base + n) * LL + col];
        s += v;
        m = fmaxf(m, v);
    }
    ssum[part][col] = s;
    smax[part][col] = m;
    __syncthreads();
    if (part == 0) {
        for (int p = 1; p < 8; p++) {
            s += ssum[p][col];
            m = fmaxf(m, smax[p][col]);
        }
        g_pooled[g * 300 + col] = s;
        g_pooled[g * 300 + 100 + col] = s / 3200.0f;
        g_pooled[g * 300 + 200 + col] = m;
    }
}

// ---------------------------------------------------------------------------
// head MLP: [8,300] -> relu 100 -> relu 100 -> 1. One block, 128 threads.
__global__ void final_kernel(const float* __restrict__ W1, const float* __restrict__ b1,
                             const float* __restrict__ W2, const float* __restrict__ b2,
                             const float* __restrict__ W3, const float* __restrict__ b3,
                             float* __restrict__ out) {
    __shared__ float sp[GB * 300];
    __shared__ float t1[GB * 100];
    int j = threadIdx.x;
    for (int i = j; i < GB * 300; i += blockDim.x) sp[i] = g_pooled[i];
    __syncthreads();

    if (j < 100) {
        float acc[GB];
#pragma unroll
        for (int r = 0; r < GB; r++) acc[r] = b1[j];
        for (int k = 0; k < 300; k++) {
            float w = W1[k * 100 + j];
#pragma unroll
            for (int r = 0; r < GB; r++) acc[r] = fmaf(sp[r * 300 + k], w, acc[r]);
        }
#pragma unroll
        for (int r = 0; r < GB; r++) t1[r * 100 + j] = fmaxf(acc[r], 0.f);
    }
    __syncthreads();

    float acc2[GB];
    if (j < 100) {
#pragma unroll
        for (int r = 0; r < GB; r++) acc2[r] = b2[j];
        for (int k = 0; k < 100; k++) {
            float w = W2[k * 100 + j];
#pragma unroll
            for (int r = 0; r < GB; r++) acc2[r] = fmaf(t1[r * 100 + k], w, acc2[r]);
        }
    }
    __syncthreads();  // all reads of t1 done
    if (j < 100) {
#pragma unroll
        for (int r = 0; r < GB; r++) sp[r * 100 + j] = fmaxf(acc2[r], 0.f);
    }
    __syncthreads();

    if (j < GB) {
        float s = b3[0];
        for (int k = 0; k < 100; k++) s = fmaf(sp[j * 100 + k], W3[k], s);
        out[j] = s;
    }
}

// ---------------------------------------------------------------------------
extern "C" void kernel_launch(void* const* d_in, const int* in_sizes, int n_in,
                              void* d_out, int out_size) {
    const float* x        = (const float*)d_in[0];
    const int*   eidx     = (const int*)d_in[1];   // [2,E]: row0=src, row1=dst
    const float* l0_W1 = (const float*)d_in[3];
    const float* l0_b1 = (const float*)d_in[4];
    const float* l0_W2 = (const float*)d_in[5];
    const float* l0_b2 = (const float*)d_in[6];
    const float* l0_W3 = (const float*)d_in[7];
    const float* l0_b3 = (const float*)d_in[8];
    const float* l1_W1 = (const float*)d_in[9];
    const float* l1_b1 = (const float*)d_in[10];
    const float* l1_W2 = (const float*)d_in[11];
    const float* l1_b2 = (const float*)d_in[12];
    const float* l1_W3 = (const float*)d_in[13];
    const float* l1_b3 = (const float*)d_in[14];
    const float* lin_W1 = (const float*)d_in[15];
    const float* lin_b1 = (const float*)d_in[16];
    const float* lin_W2 = (const float*)d_in[17];
    const float* lin_b2 = (const float*)d_in[18];
    const float* lin_W3 = (const float*)d_in[19];
    const float* lin_b3 = (const float*)d_in[20];

    const int* src = eidx;  // first row of edge_index

    // ---- layer 0 ----
    front_kernel<<<NN / 16, 300>>>(x, FF, l0_W1, l0_b1, 0);
    gemm_mid<<<dim3(3, EE / 128), 320>>>(src, l0_W2, l0_b2);
    gemm_out<<<EE / 128, 320>>>(l0_W3, l0_b3);
    // ---- layer 1 ----
    front_kernel<<<NN / 16, 300>>>(nullptr, LL, l1_W1, l1_b1, 1);
    gemm_mid<<<dim3(3, EE / 128), 320>>>(src, l1_W2, l1_b2);
    gemm_out<<<EE / 128, 320>>>(l1_W3, l1_b3);
    // ---- pooling + head ----
    pool_kernel<<<GB, 800>>>();
    final_kernel<<<1, 128>>>(lin_W1, lin_b1, lin_W2, lin_b2, lin_W3, lin_b3,
                             (float*)d_out);
}